// round 12
// baseline (speedup 1.0000x reference)
#include <cuda_runtime.h>
#include <cuda_fp16.h>
#include <mma.h>
#include <cstdint>

using namespace nvcuda;

#define NROWS  200000
#define CCH    128
#define TM     128
#define TK     64                      // K-chunk (fp16 row = 128B)
#define NCHNK  6                       // K = 384 = 6 x 64
#define NBLK1  1563                    // ceil(200000/128)
#define BN_EPS 1e-5f
#define NCH2   25                      // ceil(1563/64)

#define A_LD   72                      // halves (144B rows)
#define B_LD   136                     // halves (272B rows)
#define A_BYTES (TM * A_LD * 2)        // 18432
#define B_BYTES (TK * B_LD * 2)        // 17408
#define BUF_STRIDE (A_BYTES + B_BYTES) // 35840
#define NSTAGE 3
#define DYN_SMEM (NSTAGE * BUF_STRIDE) // 107520 (fp32 stage 64KB fits inside)
#define CHUNK_TX (TM * 128 + B_BYTES)  // 33792 bytes per chunk

// ---------------- global scratch (allocation-free) ----------------
__device__ __half g_featH[((size_t)NROWS + 1) * CCH];    // fp16 features + zero pad row
__device__ __half g_Wp   [9 * CCH * B_LD];               // fp16 W, padded rows (136 halves)
__device__ __half g_out  [(size_t)3 * NROWS * CCH];      // 153.6 MB fp16 pre-BN outputs
__device__ float  g_part [(size_t)3 * NBLK1 * 2 * CCH];  // per-tile col {sum,sumsq}
__device__ float  g_p2   [3 * NCH2 * 2 * CCH];
__device__ float  g_scale[3 * CCH];                      // rstd*gamma
__device__ float  g_off  [3 * CCH];                      // beta - mu*rstd*gamma

// ---------------- helpers ----------------
__device__ __forceinline__ uint32_t smem_u32(const void* p) {
    return (uint32_t)__cvta_generic_to_shared(p);
}
__device__ __forceinline__ void bulk_cp(uint32_t dst, const void* src, uint32_t bytes,
                                        uint32_t mbar) {
    asm volatile(
        "cp.async.bulk.shared::cluster.global.mbarrier::complete_tx::bytes "
        "[%0], [%1], %2, [%3];"
        :: "r"(dst), "l"(src), "r"(bytes), "r"(mbar) : "memory");
}
__device__ __forceinline__ void mbar_init(uint32_t mbar, uint32_t cnt) {
    asm volatile("mbarrier.init.shared.b64 [%0], %1;" :: "r"(mbar), "r"(cnt) : "memory");
}
__device__ __forceinline__ void mbar_expect(uint32_t mbar, uint32_t bytes) {
    asm volatile("mbarrier.arrive.expect_tx.shared.b64 _, [%0], %1;"
                 :: "r"(mbar), "r"(bytes) : "memory");
}
__device__ __forceinline__ void mbar_wait(uint32_t mbar, uint32_t parity) {
    uint32_t done;
    asm volatile(
        "{\n\t.reg .pred p;\n\t"
        "mbarrier.try_wait.parity.acquire.cta.shared::cta.b64 p, [%1], %2;\n\t"
        "selp.b32 %0, 1, 0, p;\n\t}"
        : "=r"(done) : "r"(mbar), "r"(parity) : "memory");
    if (!done) {
        asm volatile(
            "{\n\t.reg .pred P1;\n\t"
            "WAIT_LOOP_%=:\n\t"
            "mbarrier.try_wait.parity.acquire.cta.shared::cta.b64 P1, [%0], %1, 0x989680;\n\t"
            "@P1 bra.uni WAIT_DONE_%=;\n\t"
            "bra.uni WAIT_LOOP_%=;\n\t"
            "WAIT_DONE_%=:\n\t}"
            :: "r"(mbar), "r"(parity) : "memory");
    }
}

// ---------------------------------------------------------------------------
// K0: fp32->fp16 preconversion: features, zero pad row, padded W image
// ---------------------------------------------------------------------------
__global__ __launch_bounds__(256) void k0_prep(const float* __restrict__ feat,
                                               const float* __restrict__ W)
{
    size_t i = (size_t)blockIdx.x * 256 + threadIdx.x;
    const size_t nfeat4 = (size_t)NROWS * CCH / 4;        // 6.4M
    if (i < nfeat4) {
        float4 v = ((const float4*)feat)[i];
        __half2 h0 = __floats2half2_rn(v.x, v.y);
        __half2 h1 = __floats2half2_rn(v.z, v.w);
        *(uint2*)(g_featH + i * 4) = make_uint2(*(uint32_t*)&h0, *(uint32_t*)&h1);
    } else if (i < nfeat4 + 32) {
        size_t j = i - nfeat4;                            // zero pad row (row NROWS)
        *(uint2*)(g_featH + (size_t)NROWS * CCH + j * 4) = make_uint2(0u, 0u);
    } else {
        size_t j = i - nfeat4 - 32;                       // W: [img][k][n4], 36864 float4
        if (j >= 9 * CCH * CCH / 4) return;
        float4 v = ((const float4*)W)[j];
        int n4  = (int)(j & 31);
        int k   = (int)((j >> 5) & 127);
        int img = (int)(j >> 12);
        __half2 h0 = __floats2half2_rn(v.x, v.y);
        __half2 h1 = __floats2half2_rn(v.z, v.w);
        *(uint2*)(g_Wp + (size_t)img * CCH * B_LD + k * B_LD + n4 * 4) =
            make_uint2(*(uint32_t*)&h0, *(uint32_t*)&h1);
    }
}

// ---------------------------------------------------------------------------
// K1: per (axis, 128-row tile): out = sum_seg gather(A_seg) @ W[a,seg]
// fp16 wmma m16n16k16, K in 6 chunks of 64.
// Loads via cp.async.bulk: 128 x 128B gathered A rows + 1 x 17408B B chunk,
// 3-stage mbarrier pipeline (129 bulk ops per chunk vs 2048 cp.async.16B).
// ---------------------------------------------------------------------------
__global__ void __launch_bounds__(256, 2)
k1_gemm(const int* __restrict__ nb)
{
    const int a    = blockIdx.y;
    const int row0 = blockIdx.x * TM;
    const int t    = threadIdx.x;
    const int warp = t >> 5;
    const int mg   = warp >> 2;     // 0..1 : 64-row half
    const int ng   = warp & 3;      // 0..3 : 32-col group

    extern __shared__ __align__(1024) char dyn[];
    const uint32_t base32 = smem_u32(dyn);

    __shared__ int   s_idx[3][TM];
    __shared__ float Pred[512];
    __shared__ __align__(8) unsigned long long s_mbar[NSTAGE];

    if (t < TM) {
        int gr = row0 + t;
        bool ok = gr < NROWS;
        // sentinel / out-of-range rows -> zero pad row NROWS
        s_idx[1][t] = ok ? gr : NROWS;
        s_idx[0][t] = ok ? nb[(size_t)(a * 2 + 0) * NROWS + gr] : NROWS;
        s_idx[2][t] = ok ? nb[(size_t)(a * 2 + 1) * NROWS + gr] : NROWS;
    }
    if (t == 0) {
#pragma unroll
        for (int s = 0; s < NSTAGE; s++) mbar_init(smem_u32(&s_mbar[s]), 1);
        mbar_expect(smem_u32(&s_mbar[0]), CHUNK_TX);
        mbar_expect(smem_u32(&s_mbar[1]), CHUNK_TX);
    }
    __syncthreads();

    auto issue_chunk = [&](int i) {
        const int seg = i >> 1;
        const int kk  = (i & 1) * TK;
        const int buf = i % NSTAGE;
        const uint32_t abase = base32 + buf * BUF_STRIDE;
        const uint32_t mb    = smem_u32(&s_mbar[buf]);
        if (t < TM) {
            int idx = s_idx[seg][t];
            bulk_cp(abase + t * (A_LD * 2),
                    g_featH + (size_t)idx * CCH + kk, 128u, mb);
        } else if (t == TM) {
            bulk_cp(abase + A_BYTES,
                    g_Wp + (size_t)(a * 3 + seg) * CCH * B_LD + kk * B_LD,
                    (uint32_t)B_BYTES, mb);
        }
    };

    wmma::fragment<wmma::accumulator, 16, 16, 16, float> acc[4][2];
#pragma unroll
    for (int i = 0; i < 4; i++)
#pragma unroll
        for (int j = 0; j < 2; j++) wmma::fill_fragment(acc[i][j], 0.0f);

    issue_chunk(0);
    issue_chunk(1);

    for (int i = 0; i < NCHNK; i++) {
        mbar_wait(smem_u32(&s_mbar[i % NSTAGE]), (i / NSTAGE) & 1);
        // re-arm the barrier of the buffer we'll fill with chunk i+2
        // (its previous chunk i-1 completed; ordered before issues by the sync below)
        if (i + 2 < NCHNK && t == 0)
            mbar_expect(smem_u32(&s_mbar[(i + 2) % NSTAGE]), CHUNK_TX);

        const int buf = i % NSTAGE;
        const half* As = (const half*)(dyn + buf * BUF_STRIDE);
        const half* Bs = (const half*)(dyn + buf * BUF_STRIDE + A_BYTES);
#pragma unroll
        for (int ks = 0; ks < 4; ks++) {
            wmma::fragment<wmma::matrix_a, 16, 16, 16, half, wmma::row_major> af[4];
#pragma unroll
            for (int q = 0; q < 4; q++)
                wmma::load_matrix_sync(af[q], As + (mg * 64 + q * 16) * A_LD + ks * 16, A_LD);
#pragma unroll
            for (int j = 0; j < 2; j++) {
                wmma::fragment<wmma::matrix_b, 16, 16, 16, half, wmma::row_major> bf;
                wmma::load_matrix_sync(bf, Bs + (ks * 16) * B_LD + ng * 32 + j * 16, B_LD);
#pragma unroll
                for (int q = 0; q < 4; q++)
                    wmma::mma_sync(acc[q][j], af[q], bf, acc[q][j]);
            }
        }
        __syncthreads();                   // chunk i consumed by all warps
        if (i + 2 < NCHNK) issue_chunk(i + 2);
    }

    // ---- epilogue: fp32 stage in smem (reuses pipeline buffers)
    float* stage = (float*)dyn;               // [128][128] fp32 = 64KB
#pragma unroll
    for (int q = 0; q < 4; q++)
#pragma unroll
        for (int j = 0; j < 2; j++)
            wmma::store_matrix_sync(stage + (mg * 64 + q * 16) * CCH + ng * 32 + j * 16,
                                    acc[q][j], CCH, wmma::mem_row_major);
    __syncthreads();

    const int valid = min(TM, NROWS - row0);

    // BN partials (pad rows are exact zeros)
    {
        int col = t & 127, part = t >> 7;
        float s = 0.f, s2 = 0.f;
        const float* p = stage + col;
#pragma unroll 8
        for (int r = part * 64; r < part * 64 + 64; r++) {
            float v = p[r * CCH];
            s += v; s2 += v * v;
        }
        Pred[part * 256 + col]       = s;
        Pred[part * 256 + 128 + col] = s2;
    }
    // fp16 store of the tile (coalesced 8B stores)
    {
        __half* gp = g_out + ((size_t)a * NROWS + row0) * CCH;
#pragma unroll
        for (int it = 0; it < 16; it++) {
            int vid = t + it * 256;            // 0..4095
            int r   = vid >> 5;
            int u   = vid & 31;
            if (r < valid) {
                const float* sp = stage + r * CCH + u * 4;
                __half2 h0 = __floats2half2_rn(sp[0], sp[1]);
                __half2 h1 = __floats2half2_rn(sp[2], sp[3]);
                *(uint2*)(gp + (size_t)r * CCH + u * 4) =
                    make_uint2(*(uint32_t*)&h0, *(uint32_t*)&h1);
            }
        }
    }
    __syncthreads();
    if (t < CCH) {
        g_part[(((size_t)a * NBLK1 + blockIdx.x) * 2 + 0) * CCH + t] = Pred[t] + Pred[256 + t];
        g_part[(((size_t)a * NBLK1 + blockIdx.x) * 2 + 1) * CCH + t] = Pred[128 + t] + Pred[384 + t];
    }
}

// ---------------------------------------------------------------------------
// K2a/K2b: deterministic two-stage BN reduction; fold BN into scale/offset
// ---------------------------------------------------------------------------
__global__ __launch_bounds__(256) void k2a()
{
    const int a = blockIdx.x, g = blockIdx.y, t = threadIdx.x;
    const int s = t >> 7, c = t & 127;
    const int b1 = min((g + 1) * 64, NBLK1);
    float acc = 0.f;
    for (int b = g * 64; b < b1; b++)
        acc += g_part[(((size_t)a * NBLK1 + b) * 2 + s) * CCH + c];
    g_p2[((a * NCH2 + g) * 2 + s) * CCH + c] = acc;
}
__global__ __launch_bounds__(128) void k2b(const float* __restrict__ gamma,
                                           const float* __restrict__ beta)
{
    const int a = blockIdx.x, t = threadIdx.x;   // t = channel
    double s = 0.0, s2 = 0.0;
    for (int g = 0; g < NCH2; g++) {
        s  += (double)g_p2[((a * NCH2 + g) * 2 + 0) * CCH + t];
        s2 += (double)g_p2[((a * NCH2 + g) * 2 + 1) * CCH + t];
    }
    double mu  = s / (double)NROWS;
    double var = s2 / (double)NROWS - mu * mu;
    float rstd = rsqrtf((float)var + BN_EPS);
    float sc   = rstd * gamma[a * CCH + t];
    g_scale[a * CCH + t] = sc;
    g_off  [a * CCH + t] = beta[a * CCH + t] - (float)mu * sc;
}

// ---------------------------------------------------------------------------
// K3: out = featH * sum_a sigmoid(o_a * sc[a] + off[a])
// ---------------------------------------------------------------------------
__global__ __launch_bounds__(256) void k3_final(float* __restrict__ out)
{
    const size_t i  = (size_t)blockIdx.x * 256 + threadIdx.x;  // 4-elem group index
    const int cbase = (int)(i & 31) * 4;

    uint2 fh = *(const uint2*)(g_featH + i * 4);
    __half2 f01 = *(__half2*)&fh.x;
    __half2 f23 = *(__half2*)&fh.y;
    float f[4] = { __low2float(f01), __high2float(f01),
                   __low2float(f23), __high2float(f23) };
    float acc[4] = { 0.f, 0.f, 0.f, 0.f };

#pragma unroll
    for (int a = 0; a < 3; a++) {
        uint2 h = *(const uint2*)(g_out + (size_t)a * NROWS * CCH + i * 4);
        __half2 h01 = *(__half2*)&h.x;
        __half2 h23 = *(__half2*)&h.y;
        float o[4] = { __low2float(h01), __high2float(h01),
                       __low2float(h23), __high2float(h23) };
#pragma unroll
        for (int j = 0; j < 4; j++) {
            int c = cbase + j;
            float x = fmaf(o[j], g_scale[a * CCH + c], g_off[a * CCH + c]);
            acc[j] += 1.0f / (1.0f + __expf(-x));
        }
    }
    ((float4*)out)[i] = make_float4(acc[0] * f[0], acc[1] * f[1],
                                    acc[2] * f[2], acc[3] * f[3]);
}

// ---------------------------------------------------------------------------
extern "C" void kernel_launch(void* const* d_in, const int* in_sizes, int n_in,
                              void* d_out, int out_size)
{
    const float* feat  = (const float*)d_in[0];
    const int*   nb    = (const int*)  d_in[1];
    const float* W     = (const float*)d_in[2];
    const float* gamma = (const float*)d_in[3];
    const float* beta  = (const float*)d_in[4];

    cudaFuncSetAttribute(k1_gemm, cudaFuncAttributeMaxDynamicSharedMemorySize, DYN_SMEM);

    k0_prep<<<25145, 256>>>(feat, W);            // feat + pad row + padded W
    dim3 g1(NBLK1, 3);
    k1_gemm<<<g1, 256, DYN_SMEM>>>(nb);
    dim3 g2(3, NCH2);
    k2a<<<g2, 256>>>();
    k2b<<<3, 128>>>(gamma, beta);
    k3_final<<<25000, 256>>>((float*)d_out);
}